// round 8
// baseline (speedup 1.0000x reference)
#include <cuda_runtime.h>

// adapt_smoothing: out[b,s,f] = sum_{l=0..24} w[l] * x[b, max(s+l-24,0), f]
// x: [B=32, S=4096, F=512] fp32, w: [K=25] fp32.
//
// v7 = v5 core + traffic reduction (v6 lesson: we are BW-bound; wave balance
// self-corrects via dynamic HBM sharing, total bytes rule).
//  - S_TILE=525, 8 chunks: per-chunk history overhead 25/525 = 4.8% instead
//    of v5's 12.5%; reads drop 4725 -> 4400 row-equivs.
//  - skip-issue: no cp.async for overhang rows (t >= S_DIM); consumer already
//    guards those outputs. Saves another 104 row-reads per column.
//  Net traffic -4.9% vs v5. Pipeline unchanged: cp.async FIFO 8B/thread/row,
//  DEPTH=6 of NSB=8 batch slots, empty-group commits in drain, LDS.64 ->
//  statically-indexed 25-slot ring, packed fma.rn.f32x2, no barriers.

#define B_DIM  32
#define S_DIM  4096
#define F_DIM  512
#define K_DIM  25
#define P_DIM  (F_DIM / 2)    // 256 u64 columns total
#define HALF_P 128            // u64 columns per block
#define S_TILE 525            // outputs per chunk (multiple of 25)
#define N_CHUNK 8             // 8*525 = 4200 >= 4096
#define ROWS   (S_TILE + K_DIM)   // 550 staged rows per chunk
#define BATCH  5
#define NBATCH (ROWS / BATCH) // 110
#define NSB    8              // smem ring slots (in batches)
#define DEPTH  6              // batches in flight (30 rows)

typedef unsigned long long u64;

__device__ __forceinline__ u64 pack2(float v) {
    union { float f[2]; u64 u; } c;
    c.f[0] = v; c.f[1] = v;
    return c.u;
}
__device__ __forceinline__ u64 fma2(u64 a, u64 b, u64 c) {
    u64 d; asm("fma.rn.f32x2 %0, %1, %2, %3;" : "=l"(d) : "l"(a), "l"(b), "l"(c)); return d;
}
__device__ __forceinline__ u64 add2(u64 a, u64 b) {
    u64 d; asm("add.rn.f32x2 %0, %1, %2;" : "=l"(d) : "l"(a), "l"(b)); return d;
}

__global__ __launch_bounds__(128, 4) void adapt_smoothing_kernel(
    const float* __restrict__ x,
    const float* __restrict__ w,
    float* __restrict__ out)
{
    __shared__ u64 stage[NSB * BATCH * HALF_P];   // 40 KB

    const int tid = threadIdx.x;
    const int fp  = blockIdx.x * HALF_P + tid;    // u64 column, 0..255
    const int s0  = blockIdx.y * S_TILE;          // multiple of 25
    const int bz  = blockIdx.z;

    const u64* __restrict__ xv = (const u64*)x;
    u64* __restrict__ ov = (u64*)out;
    const int boff = bz * (S_DIM * P_DIM) + fp;   // max ~33.5M, fits int

    // Packed broadcast weights (both f32 halves = w[l]).
    u64 pw[K_DIM];
#pragma unroll
    for (int l = 0; l < K_DIM; ++l) pw[l] = pack2(__ldg(&w[l]));

    // Producer: stage batch `bat` (5 rows, 8B per thread per row).
    //  - t < 0       : clamp to row 0 (history edge padding) -- must load.
    //  - t >= S_DIM  : SKIP the cp.async (consumer guards those outputs;
    //                  smem garbage is never read into a store).
    //  - bat >= NBATCH: commit an EMPTY group so the "committed == bat+DEPTH"
    //                  invariant holds through the drain phase.
    auto issue_batch = [&](int bat) {
        if (bat < NBATCH) {
            const int base_r = bat * BATCH;
            u64* dst = &stage[(bat & (NSB - 1)) * (BATCH * HALF_P) + tid];
#pragma unroll
            for (int rr = 0; rr < BATCH; ++rr) {
                int t = s0 - K_DIM + base_r + rr;           // row timestep
                if (t < S_DIM) {
                    t = t < 0 ? 0 : t;                      // history edge clamp
                    const u64* src = &xv[boff + t * P_DIM];
                    unsigned saddr = (unsigned)__cvta_generic_to_shared(dst + rr * HALF_P);
                    asm volatile("cp.async.ca.shared.global [%0], [%1], 8;\n"
                                 :: "r"(saddr), "l"(src));
                }
            }
        }
        asm volatile("cp.async.commit_group;\n");
    };

    // Prologue: DEPTH batches in flight.
#pragma unroll
    for (int bq = 0; bq < DEPTH; ++bq) issue_batch(bq);

    u64 ring[K_DIM];   // ring[t % 25] = x[b, t, col]

    for (int bb = 0; bb < NBATCH / 5; ++bb) {     // 22 outer iterations
#pragma unroll
        for (int sub = 0; sub < 5; ++sub) {       // 5 batches => 25 rows, static
            const int bat = bb * 5 + sub;

            // Groups committed == bat + DEPTH, so wait_group(DEPTH-1) proves
            // groups 0..bat are complete.
            asm volatile("cp.async.wait_group %0;\n" :: "n"(DEPTH - 1));

            // Refill (or empty-commit in the drain phase).
            issue_batch(bat + DEPTH);

            const u64* src = &stage[(bat & (NSB - 1)) * (BATCH * HALF_P) + tid];
#pragma unroll
            for (int rr = 0; rr < BATCH; ++rr) {
                const int p = sub * BATCH + rr;   // static 0..24 == r % 25
                const int r = bat * BATCH + rr;
                const int t = s0 - K_DIM + r;

                ring[p] = src[rr * HALF_P];       // LDS.64 (own bytes)

                if (r >= K_DIM && t < S_DIM) {
                    // out[t] = sum_l pw[l] (*) ring[(p+1+l) % 25]
                    u64 a0 = 0ULL, a1 = 0ULL, a2 = 0ULL, a3 = 0ULL;
#pragma unroll
                    for (int l = 0; l < K_DIM; l += 4) {
                        a0 = fma2(pw[l], ring[(p + 1 + l) % K_DIM], a0);
                        if (l + 1 < K_DIM) a1 = fma2(pw[l + 1], ring[(p + 2 + l) % K_DIM], a1);
                        if (l + 2 < K_DIM) a2 = fma2(pw[l + 2], ring[(p + 3 + l) % K_DIM], a2);
                        if (l + 3 < K_DIM) a3 = fma2(pw[l + 3], ring[(p + 4 + l) % K_DIM], a3);
                    }
                    ov[boff + t * P_DIM] = add2(add2(a0, a1), add2(a2, a3));
                }
            }
        }
    }
}

extern "C" void kernel_launch(void* const* d_in, const int* in_sizes, int n_in,
                              void* d_out, int out_size)
{
    const float* x = (const float*)d_in[0];
    const float* w = (const float*)d_in[1];
    float* out = (float*)d_out;

    dim3 grid(P_DIM / HALF_P, N_CHUNK, B_DIM);    // (2, 8, 32) = 512
    dim3 block(HALF_P);
    adapt_smoothing_kernel<<<grid, block>>>(x, w, out);
}

// round 9
// speedup vs baseline: 1.0850x; 1.0850x over previous
#include <cuda_runtime.h>

// adapt_smoothing: out[b,s,f] = sum_{l=0..24} w[l] * x[b, max(s+l-24,0), f]
// x: [B=32, S=4096, F=512] fp32, w: [K=25] fp32.
//
// v8 = v5 (best: 94.7us, grid 1344) + two concurrency-neutral tweaks:
//  - skip-issue for overhang rows (t >= S_DIM) in the last chunk: -1.2%
//    traffic (safe: garbage ring slots only feed store-guarded outputs;
//    validated in v7).
//  - DEPTH 6 -> 7: 35 rows in flight per thread (+17% MLP). Slot-reuse
//    distance 7 < NSB=8 stays safe without barriers: the LDS of batch bat-1
//    executed in program order before the cp.async refilling its slot issues.
// v6/v7 lessons encoded: BW-bound AND concurrency-sensitive; grid ~1344
// (2-3 waves at 4 CTAs/SM) is the empirical sweet spot -- do not shrink grid.

#define B_DIM  32
#define S_DIM  4096
#define F_DIM  512
#define K_DIM  25
#define P_DIM  (F_DIM / 2)    // 256 u64 columns total
#define HALF_P 128            // u64 columns per block
#define S_TILE 200            // outputs per chunk (multiple of 25)
#define N_CHUNK 21            // 21*200 = 4200 >= 4096 ; grid = 2*21*32 = 1344
#define ROWS   (S_TILE + K_DIM)   // 225 staged rows per chunk
#define BATCH  5
#define NBATCH (ROWS / BATCH) // 45
#define NSB    8              // smem ring slots (in batches)
#define DEPTH  7              // batches in flight (35 rows)

typedef unsigned long long u64;

__device__ __forceinline__ u64 pack2(float v) {
    union { float f[2]; u64 u; } c;
    c.f[0] = v; c.f[1] = v;
    return c.u;
}
__device__ __forceinline__ u64 fma2(u64 a, u64 b, u64 c) {
    u64 d; asm("fma.rn.f32x2 %0, %1, %2, %3;" : "=l"(d) : "l"(a), "l"(b), "l"(c)); return d;
}
__device__ __forceinline__ u64 add2(u64 a, u64 b) {
    u64 d; asm("add.rn.f32x2 %0, %1, %2;" : "=l"(d) : "l"(a), "l"(b)); return d;
}

__global__ __launch_bounds__(128, 4) void adapt_smoothing_kernel(
    const float* __restrict__ x,
    const float* __restrict__ w,
    float* __restrict__ out)
{
    __shared__ u64 stage[NSB * BATCH * HALF_P];   // 40 KB

    const int tid = threadIdx.x;
    const int fp  = blockIdx.x * HALF_P + tid;    // u64 column, 0..255
    const int s0  = blockIdx.y * S_TILE;          // multiple of 25
    const int bz  = blockIdx.z;

    const u64* __restrict__ xv = (const u64*)x;
    u64* __restrict__ ov = (u64*)out;
    const int boff = bz * (S_DIM * P_DIM) + fp;   // max ~33.5M, fits int

    // Packed broadcast weights (both f32 halves = w[l]).
    u64 pw[K_DIM];
#pragma unroll
    for (int l = 0; l < K_DIM; ++l) pw[l] = pack2(__ldg(&w[l]));

    // Producer: stage batch `bat` (5 rows, 8B per thread per row).
    //  - t < 0       : clamp to row 0 (history edge padding).
    //  - t >= S_DIM  : SKIP the cp.async (outputs there are store-guarded).
    //  - bat >= NBATCH: commit an EMPTY group to keep the
    //                   "committed == bat + DEPTH" invariant in the drain.
    auto issue_batch = [&](int bat) {
        if (bat < NBATCH) {
            const int base_r = bat * BATCH;
            u64* dst = &stage[(bat & (NSB - 1)) * (BATCH * HALF_P) + tid];
#pragma unroll
            for (int rr = 0; rr < BATCH; ++rr) {
                int t = s0 - K_DIM + base_r + rr;           // row timestep
                if (t < S_DIM) {
                    t = t < 0 ? 0 : t;                      // history edge clamp
                    const u64* src = &xv[boff + t * P_DIM];
                    unsigned saddr = (unsigned)__cvta_generic_to_shared(dst + rr * HALF_P);
                    asm volatile("cp.async.ca.shared.global [%0], [%1], 8;\n"
                                 :: "r"(saddr), "l"(src));
                }
            }
        }
        asm volatile("cp.async.commit_group;\n");
    };

    // Prologue: DEPTH batches in flight.
#pragma unroll
    for (int bq = 0; bq < DEPTH; ++bq) issue_batch(bq);

    u64 ring[K_DIM];   // ring[t % 25] = x[b, t, col]

    for (int bb = 0; bb < NBATCH / 5; ++bb) {     // 9 outer iterations
#pragma unroll
        for (int sub = 0; sub < 5; ++sub) {       // 5 batches => 25 rows, static
            const int bat = bb * 5 + sub;

            // Groups committed == bat + DEPTH, so wait_group(DEPTH-1) proves
            // groups 0..bat are complete.
            asm volatile("cp.async.wait_group %0;\n" :: "n"(DEPTH - 1));

            // Refill (or empty-commit in the drain phase).
            issue_batch(bat + DEPTH);

            const u64* src = &stage[(bat & (NSB - 1)) * (BATCH * HALF_P) + tid];
#pragma unroll
            for (int rr = 0; rr < BATCH; ++rr) {
                const int p = sub * BATCH + rr;   // static 0..24 == r % 25
                const int r = bat * BATCH + rr;
                const int t = s0 - K_DIM + r;

                ring[p] = src[rr * HALF_P];       // LDS.64 (own bytes)

                if (r >= K_DIM && t < S_DIM) {
                    // out[t] = sum_l pw[l] (*) ring[(p+1+l) % 25]
                    u64 a0 = 0ULL, a1 = 0ULL, a2 = 0ULL, a3 = 0ULL;
#pragma unroll
                    for (int l = 0; l < K_DIM; l += 4) {
                        a0 = fma2(pw[l], ring[(p + 1 + l) % K_DIM], a0);
                        if (l + 1 < K_DIM) a1 = fma2(pw[l + 1], ring[(p + 2 + l) % K_DIM], a1);
                        if (l + 2 < K_DIM) a2 = fma2(pw[l + 2], ring[(p + 3 + l) % K_DIM], a2);
                        if (l + 3 < K_DIM) a3 = fma2(pw[l + 3], ring[(p + 4 + l) % K_DIM], a3);
                    }
                    ov[boff + t * P_DIM] = add2(add2(a0, a1), add2(a2, a3));
                }
            }
        }
    }
}

extern "C" void kernel_launch(void* const* d_in, const int* in_sizes, int n_in,
                              void* d_out, int out_size)
{
    const float* x = (const float*)d_in[0];
    const float* w = (const float*)d_in[1];
    float* out = (float*)d_out;

    dim3 grid(P_DIM / HALF_P, N_CHUNK, B_DIM);    // (2, 21, 32) = 1344
    dim3 block(HALF_P);
    adapt_smoothing_kernel<<<grid, block>>>(x, w, out);
}